// round 2
// baseline (speedup 1.0000x reference)
#include <cuda_runtime.h>

// ---------------------------------------------------------------------------
// MyRNN: 2-layer tanh RNN, B=4096, T=512, H=32, input dim 1, + Linear(32->1).
//
// Round-2 design:
//   - lane j = hidden unit j. One single-warp CTA handles NB=2 batch elements.
//   - f32x2 packing over the K dimension: weights W[j][2k],W[j][2k+1] form a
//     natural u64 -> only 48 u64 (96 regs) of resident weights per thread.
//   - layer1 runs one timestep behind layer0, so each iteration reads ONLY
//     old state {h0(i-1), h1(i-2)}: single load phase, single __syncwarp.
//   - ping-pong shared buffers; h broadcast via LDS.128 (conflict-free).
// ---------------------------------------------------------------------------

typedef unsigned long long u64;

#define B_TOT   4096
#define T_TOT   512
#define H_DIM   32
#define NB      2
#define NCTAS   (B_TOT / NB)   // 2048

__device__ __forceinline__ u64 pk2(float x, float y) {
    u64 r; asm("mov.b64 %0, {%1,%2};" : "=l"(r) : "f"(x), "f"(y)); return r;
}
__device__ __forceinline__ void upk2(u64 v, float& x, float& y) {
    asm("mov.b64 {%0,%1}, %2;" : "=f"(x), "=f"(y) : "l"(v));
}
__device__ __forceinline__ u64 ffma2(u64 a, u64 b, u64 c) {
    u64 d; asm("fma.rn.f32x2 %0, %1, %2, %3;" : "=l"(d) : "l"(a), "l"(b), "l"(c));
    return d;
}
__device__ __forceinline__ float tanh_fast(float x) {
    x = fminf(fmaxf(x, -15.0f), 15.0f);
    float e = __expf(2.0f * x);
    return __fdividef(e - 1.0f, e + 1.0f);
}

__global__ void __launch_bounds__(32, 1)
rnn_kernel(const float* __restrict__ x,
           const float* __restrict__ hstate,
           const float* __restrict__ Wih0, const float* __restrict__ Whh0,
           const float* __restrict__ bih0, const float* __restrict__ bhh0,
           const float* __restrict__ Wih1, const float* __restrict__ Whh1,
           const float* __restrict__ bih1, const float* __restrict__ bhh1,
           const float* __restrict__ Wfc,  const float* __restrict__ bfc,
           float* __restrict__ out)
{
    // ping-pong state: G0[buf][batch][j] = h0, G1 = h1
    __shared__ __align__(16) float G0[2][NB][H_DIM];
    __shared__ __align__(16) float G1[2][NB][H_DIM];

    const int j  = threadIdx.x;          // hidden unit
    const int b0 = blockIdx.x * NB;      // first batch element of this CTA

    // ---- weights: k-packed u64, natural memory layout ----
    u64 w0[H_DIM / 2], wA[H_DIM / 2], wB[H_DIM / 2];
    {
        const u64* q0 = reinterpret_cast<const u64*>(Whh0 + j * H_DIM);
        const u64* qA = reinterpret_cast<const u64*>(Wih1 + j * H_DIM);
        const u64* qB = reinterpret_cast<const u64*>(Whh1 + j * H_DIM);
#pragma unroll
        for (int q = 0; q < H_DIM / 2; q++) { w0[q] = q0[q]; wA[q] = qA[q]; wB[q] = qB[q]; }
    }
    const float wi0  = Wih0[j];
    const float bb0  = bih0[j] + bhh0[j];
    const float bb1  = bih1[j] + bhh1[j];

    // ---- initial state: h0 -> buffer 0, h1 -> buffer 1 (first read at i=1) ----
#pragma unroll
    for (int bb = 0; bb < NB; bb++) {
        G0[0][bb][j] = hstate[(b0 + bb) * H_DIM + j];
        G1[1][bb][j] = hstate[B_TOT * H_DIM + (b0 + bb) * H_DIM + j];
    }
    __syncwarp();

    // =================== i = 0 : layer0 only ===================
    {
        float xi[NB]; u64 a0[NB];
#pragma unroll
        for (int bb = 0; bb < NB; bb++) {
            xi[bb] = __ldg(&x[(b0 + bb) * T_TOT]);
            a0[bb] = 0ull;
        }
#pragma unroll
        for (int q = 0; q < 8; q++) {
#pragma unroll
            for (int bb = 0; bb < NB; bb++) {
                ulonglong2 g = *reinterpret_cast<const ulonglong2*>(&G0[0][bb][4 * q]);
                a0[bb] = ffma2(w0[2 * q],     g.x, a0[bb]);
                a0[bb] = ffma2(w0[2 * q + 1], g.y, a0[bb]);
            }
        }
#pragma unroll
        for (int bb = 0; bb < NB; bb++) {
            float lo, hi; upk2(a0[bb], lo, hi);
            G0[1][bb][j] = tanh_fast(lo + hi + wi0 * xi[bb] + bb0);
        }
        __syncwarp();
    }

    // =================== main loop i = 1 .. T-1 ===================
#pragma unroll 1
    for (int i = 1; i < T_TOT; i++) {
        const int rp = i & 1, wp = rp ^ 1;

        float xi[NB]; u64 a0[NB], aA[NB], aB[NB];
#pragma unroll
        for (int bb = 0; bb < NB; bb++) {
            xi[bb] = __ldg(&x[(b0 + bb) * T_TOT + i]);
            a0[bb] = 0ull; aA[bb] = 0ull; aB[bb] = 0ull;
        }

#pragma unroll
        for (int q = 0; q < 8; q++) {
#pragma unroll
            for (int bb = 0; bb < NB; bb++) {
                ulonglong2 g = *reinterpret_cast<const ulonglong2*>(&G0[rp][bb][4 * q]);
                a0[bb] = ffma2(w0[2 * q],     g.x, a0[bb]);
                a0[bb] = ffma2(w0[2 * q + 1], g.y, a0[bb]);
                aA[bb] = ffma2(wA[2 * q],     g.x, aA[bb]);
                aA[bb] = ffma2(wA[2 * q + 1], g.y, aA[bb]);
                ulonglong2 h = *reinterpret_cast<const ulonglong2*>(&G1[rp][bb][4 * q]);
                aB[bb] = ffma2(wB[2 * q],     h.x, aB[bb]);
                aB[bb] = ffma2(wB[2 * q + 1], h.y, aB[bb]);
            }
        }

#pragma unroll
        for (int bb = 0; bb < NB; bb++) {
            float l0, h0s; upk2(a0[bb], l0, h0s);
            float lA, hA;  upk2(aA[bb], lA, hA);
            float lB, hB;  upk2(aB[bb], lB, hB);
            G0[wp][bb][j] = tanh_fast(l0 + h0s + wi0 * xi[bb] + bb0);
            G1[wp][bb][j] = tanh_fast((lA + hA) + (lB + hB) + bb1);
        }
        __syncwarp();
    }

    // =================== i = T : layer1 only ===================
    float h0last[NB], h1last[NB];
    {
        // T is even -> final states live in buffer rp = 0
        u64 aA[NB], aB[NB];
#pragma unroll
        for (int bb = 0; bb < NB; bb++) { aA[bb] = 0ull; aB[bb] = 0ull; }
#pragma unroll
        for (int q = 0; q < 8; q++) {
#pragma unroll
            for (int bb = 0; bb < NB; bb++) {
                ulonglong2 g = *reinterpret_cast<const ulonglong2*>(&G0[0][bb][4 * q]);
                aA[bb] = ffma2(wA[2 * q],     g.x, aA[bb]);
                aA[bb] = ffma2(wA[2 * q + 1], g.y, aA[bb]);
                ulonglong2 h = *reinterpret_cast<const ulonglong2*>(&G1[0][bb][4 * q]);
                aB[bb] = ffma2(wB[2 * q],     h.x, aB[bb]);
                aB[bb] = ffma2(wB[2 * q + 1], h.y, aB[bb]);
            }
        }
#pragma unroll
        for (int bb = 0; bb < NB; bb++) {
            float lA, hA; upk2(aA[bb], lA, hA);
            float lB, hB; upk2(aB[bb], lB, hB);
            h1last[bb] = tanh_fast((lA + hA) + (lB + hB) + bb1);
            h0last[bb] = G0[0][bb][j];
        }
    }

    // =================== outputs ===================
    const float wfcj = Wfc[j];
    const float bf   = bfc[0];
    float* h0out = out + B_TOT;
    float* h1out = out + B_TOT + B_TOT * H_DIM;

#pragma unroll
    for (int bb = 0; bb < NB; bb++) {
        const int b = b0 + bb;
        h0out[b * H_DIM + j] = h0last[bb];
        h1out[b * H_DIM + j] = h1last[bb];

        float p = h1last[bb] * wfcj;
#pragma unroll
        for (int m = 16; m > 0; m >>= 1)
            p += __shfl_xor_sync(0xffffffffu, p, m);
        if (j == 0) out[b] = p + bf;
    }
}

// ---------------------------------------------------------------------------
extern "C" void kernel_launch(void* const* d_in, const int* in_sizes, int n_in,
                              void* d_out, int out_size)
{
    const float* x      = (const float*)d_in[0];
    const float* hstate = (const float*)d_in[1];
    const float* Wih0   = (const float*)d_in[2];
    const float* Whh0   = (const float*)d_in[3];
    const float* bih0   = (const float*)d_in[4];
    const float* bhh0   = (const float*)d_in[5];
    const float* Wih1   = (const float*)d_in[6];
    const float* Whh1   = (const float*)d_in[7];
    const float* bih1   = (const float*)d_in[8];
    const float* bhh1   = (const float*)d_in[9];
    const float* Wfc    = (const float*)d_in[10];
    const float* bfc    = (const float*)d_in[11];
    float* out          = (float*)d_out;

    rnn_kernel<<<NCTAS, 32>>>(x, hstate, Wih0, Whh0, bih0, bhh0,
                              Wih1, Whh1, bih1, bhh1, Wfc, bfc, out);
}

// round 4
// speedup vs baseline: 1.0050x; 1.0050x over previous
#include <cuda_runtime.h>

// ---------------------------------------------------------------------------
// MyRNN: 2-layer tanh RNN, B=4096, T=512, H=32, input dim 1, + Linear(32->1).
//
// Round-3 design:
//   - lane j = hidden unit j. One single-warp CTA handles NB=4 batch elements
//     (1024 CTAs = single wave at ~7 CTAs/SM even with ~200 regs).
//   - f32x2 packing over K: weights are natural u64 pairs -> 48 u64 = 96 regs.
//   - layer1 skewed one timestep behind layer0: each iteration reads ONLY old
//     state {h0(i-1), h1(i-2)} -> one load phase, ONE __syncwarp per step.
//   - 192 FFMA2 per warp-step in 12 independent chains hides the serial
//     tanh/sync/LDS tail.
// ---------------------------------------------------------------------------

typedef unsigned long long u64;

#define B_TOT   4096
#define T_TOT   512
#define H_DIM   32
#define NB      4
#define NCTAS   (B_TOT / NB)   // 1024

__device__ __forceinline__ u64 pk2(float x, float y) {
    u64 r; asm("mov.b64 %0, {%1,%2};" : "=l"(r) : "f"(x), "f"(y)); return r;
}
__device__ __forceinline__ void upk2(u64 v, float& x, float& y) {
    asm("mov.b64 {%0,%1}, %2;" : "=f"(x), "=f"(y) : "l"(v));
}
__device__ __forceinline__ u64 ffma2(u64 a, u64 b, u64 c) {
    u64 d; asm("fma.rn.f32x2 %0, %1, %2, %3;" : "=l"(d) : "l"(a), "l"(b), "l"(c));
    return d;
}
__device__ __forceinline__ float tanh_fast(float x) {
    x = fminf(fmaxf(x, -15.0f), 15.0f);
    float e = __expf(2.0f * x);
    return __fdividef(e - 1.0f, e + 1.0f);
}

__global__ void __launch_bounds__(32, 1)
rnn_kernel(const float* __restrict__ x,
           const float* __restrict__ hstate,
           const float* __restrict__ Wih0, const float* __restrict__ Whh0,
           const float* __restrict__ bih0, const float* __restrict__ bhh0,
           const float* __restrict__ Wih1, const float* __restrict__ Whh1,
           const float* __restrict__ bih1, const float* __restrict__ bhh1,
           const float* __restrict__ Wfc,  const float* __restrict__ bfc,
           float* __restrict__ out)
{
    // ping-pong state: G0[buf][batch][j] = h0, G1 = h1
    __shared__ __align__(16) float G0[2][NB][H_DIM];
    __shared__ __align__(16) float G1[2][NB][H_DIM];

    const int j  = threadIdx.x;          // hidden unit
    const int b0 = blockIdx.x * NB;      // first batch element of this CTA

    // ---- weights: k-packed u64, natural memory layout (96 regs total) ----
    u64 w0[H_DIM / 2], wA[H_DIM / 2], wB[H_DIM / 2];
    {
        const u64* q0 = reinterpret_cast<const u64*>(Whh0 + j * H_DIM);
        const u64* qA = reinterpret_cast<const u64*>(Wih1 + j * H_DIM);
        const u64* qB = reinterpret_cast<const u64*>(Whh1 + j * H_DIM);
#pragma unroll
        for (int q = 0; q < H_DIM / 2; q++) { w0[q] = q0[q]; wA[q] = qA[q]; wB[q] = qB[q]; }
    }
    const float wi0  = Wih0[j];
    const float bb0  = bih0[j] + bhh0[j];
    const float bb1  = bih1[j] + bhh1[j];

    // ---- initial state: h0 -> buffer 0, h1 -> buffer 1 (first read at i=1) ----
#pragma unroll
    for (int bb = 0; bb < NB; bb++) {
        G0[0][bb][j] = hstate[(b0 + bb) * H_DIM + j];
        G1[1][bb][j] = hstate[B_TOT * H_DIM + (b0 + bb) * H_DIM + j];
    }
    __syncwarp();

    // =================== i = 0 : layer0 only ===================
    {
        float xi[NB]; u64 a0[NB];
#pragma unroll
        for (int bb = 0; bb < NB; bb++) {
            xi[bb] = __ldg(&x[(b0 + bb) * T_TOT]);
            a0[bb] = 0ull;
        }
#pragma unroll
        for (int q = 0; q < 8; q++) {
#pragma unroll
            for (int bb = 0; bb < NB; bb++) {
                ulonglong2 g = *reinterpret_cast<const ulonglong2*>(&G0[0][bb][4 * q]);
                a0[bb] = ffma2(w0[2 * q],     g.x, a0[bb]);
                a0[bb] = ffma2(w0[2 * q + 1], g.y, a0[bb]);
            }
        }
#pragma unroll
        for (int bb = 0; bb < NB; bb++) {
            float lo, hi; upk2(a0[bb], lo, hi);
            G0[1][bb][j] = tanh_fast(lo + hi + wi0 * xi[bb] + bb0);
        }
        __syncwarp();
    }

    // =================== main loop i = 1 .. T-1 ===================
#pragma unroll 1
    for (int i = 1; i < T_TOT; i++) {
        const int rp = i & 1, wp = rp ^ 1;

        float xi[NB]; u64 a0[NB], aA[NB], aB[NB];
#pragma unroll
        for (int bb = 0; bb < NB; bb++) {
            xi[bb] = __ldg(&x[(b0 + bb) * T_TOT + i]);
            a0[bb] = 0ull; aA[bb] = 0ull; aB[bb] = 0ull;
        }

#pragma unroll
        for (int q = 0; q < 8; q++) {
#pragma unroll
            for (int bb = 0; bb < NB; bb++) {
                ulonglong2 g = *reinterpret_cast<const ulonglong2*>(&G0[rp][bb][4 * q]);
                a0[bb] = ffma2(w0[2 * q],     g.x, a0[bb]);
                a0[bb] = ffma2(w0[2 * q + 1], g.y, a0[bb]);
                aA[bb] = ffma2(wA[2 * q],     g.x, aA[bb]);
                aA[bb] = ffma2(wA[2 * q + 1], g.y, aA[bb]);
                ulonglong2 h = *reinterpret_cast<const ulonglong2*>(&G1[rp][bb][4 * q]);
                aB[bb] = ffma2(wB[2 * q],     h.x, aB[bb]);
                aB[bb] = ffma2(wB[2 * q + 1], h.y, aB[bb]);
            }
        }

#pragma unroll
        for (int bb = 0; bb < NB; bb++) {
            float l0, h0s; upk2(a0[bb], l0, h0s);
            float lA, hA;  upk2(aA[bb], lA, hA);
            float lB, hB;  upk2(aB[bb], lB, hB);
            G0[wp][bb][j] = tanh_fast(l0 + h0s + wi0 * xi[bb] + bb0);
            G1[wp][bb][j] = tanh_fast((lA + hA) + (lB + hB) + bb1);
        }
        __syncwarp();
    }

    // =================== i = T : layer1 only ===================
    // T even -> final states in buffer 0: G0[0]=h0(T-1), G1[0]=h1(T-2)
    float h0last[NB], h1last[NB];
    {
        u64 aA[NB], aB[NB];
#pragma unroll
        for (int bb = 0; bb < NB; bb++) { aA[bb] = 0ull; aB[bb] = 0ull; }
#pragma unroll
        for (int q = 0; q < 8; q++) {
#pragma unroll
            for (int bb = 0; bb < NB; bb++) {
                ulonglong2 g = *reinterpret_cast<const ulonglong2*>(&G0[0][bb][4 * q]);
                aA[bb] = ffma2(wA[2 * q],     g.x, aA[bb]);
                aA[bb] = ffma2(wA[2 * q + 1], g.y, aA[bb]);
                ulonglong2 h = *reinterpret_cast<const ulonglong2*>(&G1[0][bb][4 * q]);
                aB[bb] = ffma2(wB[2 * q],     h.x, aB[bb]);
                aB[bb] = ffma2(wB[2 * q + 1], h.y, aB[bb]);
            }
        }
#pragma unroll
        for (int bb = 0; bb < NB; bb++) {
            float lA, hA; upk2(aA[bb], lA, hA);
            float lB, hB; upk2(aB[bb], lB, hB);
            h1last[bb] = tanh_fast((lA + hA) + (lB + hB) + bb1);
            h0last[bb] = G0[0][bb][j];
        }
    }

    // =================== outputs ===================
    const float wfcj = Wfc[j];
    const float bf   = bfc[0];
    float* h0out = out + B_TOT;
    float* h1out = out + B_TOT + B_TOT * H_DIM;

#pragma unroll
    for (int bb = 0; bb < NB; bb++) {
        const int b = b0 + bb;
        h0out[b * H_DIM + j] = h0last[bb];
        h1out[b * H_DIM + j] = h1last[bb];

        float p = h1last[bb] * wfcj;
#pragma unroll
        for (int m = 16; m > 0; m >>= 1)
            p += __shfl_xor_sync(0xffffffffu, p, m);
        if (j == 0) out[b] = p + bf;
    }
}

// ---------------------------------------------------------------------------
extern "C" void kernel_launch(void* const* d_in, const int* in_sizes, int n_in,
                              void* d_out, int out_size)
{
    const float* x      = (const float*)d_in[0];
    const float* hstate = (const float*)d_in[1];
    const float* Wih0   = (const float*)d_in[2];
    const float* Whh0   = (const float*)d_in[3];
    const float* bih0   = (const float*)d_in[4];
    const float* bhh0   = (const float*)d_in[5];
    const float* Wih1   = (const float*)d_in[6];
    const float* Whh1   = (const float*)d_in[7];
    const float* bih1   = (const float*)d_in[8];
    const float* bhh1   = (const float*)d_in[9];
    const float* Wfc    = (const float*)d_in[10];
    const float* bfc    = (const float*)d_in[11];
    float* out          = (float*)d_out;

    rnn_kernel<<<NCTAS, 32>>>(x, hstate, Wih0, Whh0, bih0, bhh0,
                              Wih1, Whh1, bih1, bhh1, Wfc, bfc, out);
}

// round 7
// speedup vs baseline: 1.0075x; 1.0024x over previous
#include <cuda_runtime.h>

// ---------------------------------------------------------------------------
// MyRNN: 2-layer tanh RNN, B=4096, T=512, H=32, input dim 1, + Linear(32->1).
//
// Round-6 (resubmit of R5 — infra failure, experiment never ran):
//   - 128 CTAs x 256 threads (8 warps). Warp w of CTA c owns batches
//     c*32 + w*4 .. +3  (NB=4). Exactly <=1 CTA/SM: perfectly balanced,
//     2 warps per SMSP guaranteed on every scheduler.
//   - Per-warp logic identical to R3: K-packed f32x2 weights in registers
//     (96 regs), layer1 skewed one step behind layer0 so each iteration
//     reads only old state -> single load phase, ONE __syncwarp per step.
//   - Warp-private smem state: no CTA barriers anywhere in the loop.
// ---------------------------------------------------------------------------

typedef unsigned long long u64;

#define B_TOT   4096
#define T_TOT   512
#define H_DIM   32
#define NB      4
#define WARPS   8
#define NCTAS   (B_TOT / (NB * WARPS))   // 128

__device__ __forceinline__ u64 pk2(float x, float y) {
    u64 r; asm("mov.b64 %0, {%1,%2};" : "=l"(r) : "f"(x), "f"(y)); return r;
}
__device__ __forceinline__ void upk2(u64 v, float& x, float& y) {
    asm("mov.b64 {%0,%1}, %2;" : "=f"(x), "=f"(y) : "l"(v));
}
__device__ __forceinline__ u64 ffma2(u64 a, u64 b, u64 c) {
    u64 d; asm("fma.rn.f32x2 %0, %1, %2, %3;" : "=l"(d) : "l"(a), "l"(b), "l"(c));
    return d;
}
__device__ __forceinline__ float tanh_fast(float x) {
    x = fminf(fmaxf(x, -15.0f), 15.0f);
    float e = __expf(2.0f * x);
    return __fdividef(e - 1.0f, e + 1.0f);
}

__global__ void __launch_bounds__(256, 1)
rnn_kernel(const float* __restrict__ x,
           const float* __restrict__ hstate,
           const float* __restrict__ Wih0, const float* __restrict__ Whh0,
           const float* __restrict__ bih0, const float* __restrict__ bhh0,
           const float* __restrict__ Wih1, const float* __restrict__ Whh1,
           const float* __restrict__ bih1, const float* __restrict__ bhh1,
           const float* __restrict__ Wfc,  const float* __restrict__ bfc,
           float* __restrict__ out)
{
    // warp-private ping-pong state: [warp][buf][batch][j]
    __shared__ __align__(16) float G0[WARPS][2][NB][H_DIM];
    __shared__ __align__(16) float G1[WARPS][2][NB][H_DIM];

    const int j   = threadIdx.x & 31;                 // hidden unit
    const int wid = threadIdx.x >> 5;                 // warp in CTA
    const int b0  = blockIdx.x * (NB * WARPS) + wid * NB;

    float (*g0)[NB][H_DIM] = G0[wid];
    float (*g1)[NB][H_DIM] = G1[wid];

    // ---- weights: k-packed u64, natural memory layout (96 regs total) ----
    u64 w0[H_DIM / 2], wA[H_DIM / 2], wB[H_DIM / 2];
    {
        const u64* q0 = reinterpret_cast<const u64*>(Whh0 + j * H_DIM);
        const u64* qA = reinterpret_cast<const u64*>(Wih1 + j * H_DIM);
        const u64* qB = reinterpret_cast<const u64*>(Whh1 + j * H_DIM);
#pragma unroll
        for (int q = 0; q < H_DIM / 2; q++) { w0[q] = q0[q]; wA[q] = qA[q]; wB[q] = qB[q]; }
    }
    const float wi0  = Wih0[j];
    const float bb0  = bih0[j] + bhh0[j];
    const float bb1  = bih1[j] + bhh1[j];

    // ---- initial state: h0 -> buffer 0, h1 -> buffer 1 (first read at i=1) ----
#pragma unroll
    for (int bb = 0; bb < NB; bb++) {
        g0[0][bb][j] = hstate[(b0 + bb) * H_DIM + j];
        g1[1][bb][j] = hstate[B_TOT * H_DIM + (b0 + bb) * H_DIM + j];
    }
    __syncwarp();

    // =================== i = 0 : layer0 only ===================
    {
        float xi[NB]; u64 a0[NB];
#pragma unroll
        for (int bb = 0; bb < NB; bb++) {
            xi[bb] = __ldg(&x[(b0 + bb) * T_TOT]);
            a0[bb] = 0ull;
        }
#pragma unroll
        for (int q = 0; q < 8; q++) {
#pragma unroll
            for (int bb = 0; bb < NB; bb++) {
                ulonglong2 g = *reinterpret_cast<const ulonglong2*>(&g0[0][bb][4 * q]);
                a0[bb] = ffma2(w0[2 * q],     g.x, a0[bb]);
                a0[bb] = ffma2(w0[2 * q + 1], g.y, a0[bb]);
            }
        }
#pragma unroll
        for (int bb = 0; bb < NB; bb++) {
            float lo, hi; upk2(a0[bb], lo, hi);
            g0[1][bb][j] = tanh_fast(lo + hi + wi0 * xi[bb] + bb0);
        }
        __syncwarp();
    }

    // =================== main loop i = 1 .. T-1 ===================
#pragma unroll 1
    for (int i = 1; i < T_TOT; i++) {
        const int rp = i & 1, wp = rp ^ 1;

        float xi[NB]; u64 a0[NB], aA[NB], aB[NB];
#pragma unroll
        for (int bb = 0; bb < NB; bb++) {
            xi[bb] = __ldg(&x[(b0 + bb) * T_TOT + i]);
            a0[bb] = 0ull; aA[bb] = 0ull; aB[bb] = 0ull;
        }

#pragma unroll
        for (int q = 0; q < 8; q++) {
#pragma unroll
            for (int bb = 0; bb < NB; bb++) {
                ulonglong2 g = *reinterpret_cast<const ulonglong2*>(&g0[rp][bb][4 * q]);
                a0[bb] = ffma2(w0[2 * q],     g.x, a0[bb]);
                a0[bb] = ffma2(w0[2 * q + 1], g.y, a0[bb]);
                aA[bb] = ffma2(wA[2 * q],     g.x, aA[bb]);
                aA[bb] = ffma2(wA[2 * q + 1], g.y, aA[bb]);
                ulonglong2 h = *reinterpret_cast<const ulonglong2*>(&g1[rp][bb][4 * q]);
                aB[bb] = ffma2(wB[2 * q],     h.x, aB[bb]);
                aB[bb] = ffma2(wB[2 * q + 1], h.y, aB[bb]);
            }
        }

#pragma unroll
        for (int bb = 0; bb < NB; bb++) {
            float l0, h0s; upk2(a0[bb], l0, h0s);
            float lA, hA;  upk2(aA[bb], lA, hA);
            float lB, hB;  upk2(aB[bb], lB, hB);
            g0[wp][bb][j] = tanh_fast(l0 + h0s + wi0 * xi[bb] + bb0);
            g1[wp][bb][j] = tanh_fast((lA + hA) + (lB + hB) + bb1);
        }
        __syncwarp();
    }

    // =================== i = T : layer1 only ===================
    // T even -> final states in buffer 0: g0[0]=h0(T-1), g1[0]=h1(T-2)
    float h0last[NB], h1last[NB];
    {
        u64 aA[NB], aB[NB];
#pragma unroll
        for (int bb = 0; bb < NB; bb++) { aA[bb] = 0ull; aB[bb] = 0ull; }
#pragma unroll
        for (int q = 0; q < 8; q++) {
#pragma unroll
            for (int bb = 0; bb < NB; bb++) {
                ulonglong2 g = *reinterpret_cast<const ulonglong2*>(&g0[0][bb][4 * q]);
                aA[bb] = ffma2(wA[2 * q],     g.x, aA[bb]);
                aA[bb] = ffma2(wA[2 * q + 1], g.y, aA[bb]);
                ulonglong2 h = *reinterpret_cast<const ulonglong2*>(&g1[0][bb][4 * q]);
                aB[bb] = ffma2(wB[2 * q],     h.x, aB[bb]);
                aB[bb] = ffma2(wB[2 * q + 1], h.y, aB[bb]);
            }
        }
#pragma unroll
        for (int bb = 0; bb < NB; bb++) {
            float lA, hA; upk2(aA[bb], lA, hA);
            float lB, hB; upk2(aB[bb], lB, hB);
            h1last[bb] = tanh_fast((lA + hA) + (lB + hB) + bb1);
            h0last[bb] = g0[0][bb][j];
        }
    }

    // =================== outputs ===================
    const float wfcj = Wfc[j];
    const float bf   = bfc[0];
    float* h0out = out + B_TOT;
    float* h1out = out + B_TOT + B_TOT * H_DIM;

#pragma unroll
    for (int bb = 0; bb < NB; bb++) {
        const int b = b0 + bb;
        h0out[b * H_DIM + j] = h0last[bb];
        h1out[b * H_DIM + j] = h1last[bb];

        float p = h1last[bb] * wfcj;
#pragma unroll
        for (int m = 16; m > 0; m >>= 1)
            p += __shfl_xor_sync(0xffffffffu, p, m);
        if (j == 0) out[b] = p + bf;
    }
}

// ---------------------------------------------------------------------------
extern "C" void kernel_launch(void* const* d_in, const int* in_sizes, int n_in,
                              void* d_out, int out_size)
{
    const float* x      = (const float*)d_in[0];
    const float* hstate = (const float*)d_in[1];
    const float* Wih0   = (const float*)d_in[2];
    const float* Whh0   = (const float*)d_in[3];
    const float* bih0   = (const float*)d_in[4];
    const float* bhh0   = (const float*)d_in[5];
    const float* Wih1   = (const float*)d_in[6];
    const float* Whh1   = (const float*)d_in[7];
    const float* bih1   = (const float*)d_in[8];
    const float* bhh1   = (const float*)d_in[9];
    const float* Wfc    = (const float*)d_in[10];
    const float* bfc    = (const float*)d_in[11];
    float* out          = (float*)d_out;

    rnn_kernel<<<NCTAS, 256>>>(x, hstate, Wih0, Whh0, bih0, bhh0,
                               Wih1, Whh1, bih1, bhh1, Wfc, bfc, out);
}